// round 3
// baseline (speedup 1.0000x reference)
#include <cuda_runtime.h>
#include <cuda_bf16.h>

#define BATCH 32
#define IN_H  512
#define IN_W  512
#define CH    3
#define OUT_H 224
#define OUT_W 224

#define STRIP    8                      // output rows per CTA
#define MAXROWS  22                     // max mid rows needed per strip
#define NBLK     (OUT_H / STRIP)        // 28
#define INVS     (16.0f / 7.0f)         // in/out scale (both dims) = antialias kernel radius

// dynamic smem layout (floats):
//   mid  [MAXROWS][OUT_W][CH]     = 22*224*3          = 14784
//   srow [2][CH][IN_W] ping-pong  = 2*3*512           = 3072
#define SM_MID    0
#define SM_SROW   (MAXROWS * OUT_W * CH)
#define SROW_BUF  (CH * IN_W)
#define SM_FLOATS (SM_SROW + 2 * SROW_BUF)             // 17856 floats = 71424 B

// jax.image.resize "bilinear", antialias=True, downscale by 16/7:
// sample = (o+0.5)*INVS - 0.5 ; triangle widened to radius INVS;
// weights over in-range taps, normalized to sum 1.
__device__ __forceinline__ int resize_weights(int o, int in_size, int& jlo, float w[6]) {
    const float sample = (o + 0.5f) * INVS - 0.5f;
    int lo = (int)ceilf(sample - INVS);
    int hi = (int)floorf(sample + INVS);
    if (lo < 0) lo = 0;
    if (hi > in_size - 1) hi = in_size - 1;
    const int n = hi - lo + 1;
    float sum = 0.0f;
    #pragma unroll 6
    for (int t = 0; t < n; t++) {
        float wt = 1.0f - fabsf(sample - (float)(lo + t)) * (7.0f / 16.0f);
        wt = fmaxf(wt, 0.0f);
        w[t] = wt;
        sum += wt;
    }
    const float inv = 1.0f / sum;
    #pragma unroll 6
    for (int t = 0; t < n; t++) w[t] *= inv;
    jlo = lo;
    return n;
}

__global__ __launch_bounds__(256) void fused_warp_resize_kernel(
    const float* __restrict__ images,
    const float* __restrict__ mats,
    float* __restrict__ out)
{
    extern __shared__ float sm[];
    const int tid = threadIdx.x;
    const int b   = blockIdx.y;
    const int oy0 = blockIdx.x * STRIP;

    // ---- source-resolution row range needed by this strip of 8 output rows
    const float s_first = (oy0 + 0.5f) * INVS - 0.5f;
    const float s_last  = (oy0 + STRIP - 0.5f) * INVS - 0.5f;
    int jlo = (int)ceilf(s_first - INVS);  if (jlo < 0) jlo = 0;
    int jhi = (int)floorf(s_last + INVS);  if (jhi > IN_H - 1) jhi = IN_H - 1;
    const int nrows = jhi - jlo + 1;       // <= 21

    // ---- per-CTA constants
    __shared__ float Ms[6];
    __shared__ int   vn[STRIP], vlo[STRIP];
    __shared__ float vw[STRIP][6];
    if (tid < 6) Ms[tid] = mats[b * 6 + tid];
    if (tid < STRIP) {
        int l; float w[6];
        const int n = resize_weights(oy0 + tid, IN_H, l, w);
        vn[tid]  = n;
        vlo[tid] = l - jlo;                // relative to strip base
        #pragma unroll
        for (int t = 0; t < 6; t++) vw[tid][t] = (t < n) ? w[t] : 0.0f;
    }

    // horizontal weights: ox == tid is fixed across rows -> registers, once
    int   hlo = 0, hn = 0;
    float hw[6];
    if (tid < OUT_W) hn = resize_weights(tid, IN_W, hlo, hw);

    __syncthreads();
    const float M00 = Ms[0], M01 = Ms[1], M02 = Ms[2];
    const float M10 = Ms[3], M11 = Ms[4], M12 = Ms[5];
    const float* __restrict__ img = images + (size_t)b * IN_H * IN_W * CH;

    // ---- per mid row: warp 512 px (phase 1), h-resize to 224 px (phase 2).
    // srow is double-buffered: one barrier per row. Phase-1 writes of row r+1
    // target the opposite buffer from the one phase-2 stragglers of row r read.
    for (int r = 0; r < nrows; r++) {
        float* __restrict__ srow = &sm[SM_SROW + (r & 1) * SROW_BUF];
        const float fj = (float)(jlo + r);
        const float by = fmaf(M00, fj, M02);
        const float bx = fmaf(M10, fj, M12);

        #pragma unroll
        for (int half = 0; half < 2; half++) {
            const int x = tid + half * 256;
            const float fx = (float)x;
            const float sy = fmaf(M01, fx, by);
            const float sx = fmaf(M11, fx, bx);
            const float y0f = floorf(sy);
            const float x0f = floorf(sx);
            const float wy = sy - y0f;
            const float wx = sx - x0f;
            const int y0 = (int)y0f;
            const int x0 = (int)x0f;

            float v[4][CH];
            #pragma unroll
            for (int dy = 0; dy < 2; dy++) {
                #pragma unroll
                for (int dx = 0; dx < 2; dx++) {
                    const int yi = y0 + dy;
                    const int xi = x0 + dx;
                    const bool valid = (yi >= 0) & (yi < IN_H) & (xi >= 0) & (xi < IN_W);
                    const int yc = min(max(yi, 0), IN_H - 1);
                    const int xc = min(max(xi, 0), IN_W - 1);
                    const float m = valid ? 1.0f : 0.0f;
                    const float* __restrict__ p = img + ((size_t)yc * IN_W + xc) * CH;
                    #pragma unroll
                    for (int c = 0; c < CH; c++)
                        v[dy * 2 + dx][c] = __ldg(p + c) * m;
                }
            }
            const float owx = 1.0f - wx;
            const float owy = 1.0f - wy;
            #pragma unroll
            for (int c = 0; c < CH; c++) {
                const float top = fmaf(v[0][c], owx, v[1][c] * wx);
                const float bot = fmaf(v[2][c], owx, v[3][c] * wx);
                srow[c * IN_W + x] = fmaf(top, owy, bot * wy);
            }
        }
        __syncthreads();    // srow[r&1] ready for readers

        if (tid < OUT_W) {
            float a0 = 0.0f, a1 = 0.0f, a2 = 0.0f;
            #pragma unroll 6
            for (int t = 0; t < hn; t++) {
                const float wt = hw[t];
                const int j = hlo + t;
                a0 = fmaf(wt, srow[0 * IN_W + j], a0);
                a1 = fmaf(wt, srow[1 * IN_W + j], a1);
                a2 = fmaf(wt, srow[2 * IN_W + j], a2);
            }
            float* __restrict__ md = &sm[SM_MID + (r * OUT_W + tid) * CH];
            md[0] = a0; md[1] = a1; md[2] = a2;
        }
        // no second barrier: next row writes the other srow buffer
    }
    __syncthreads();        // all mid rows written

    // ---- vertical resize strip -> 8 output rows
    const int strip_elems = STRIP * OUT_W * CH;             // 5376
    for (int e = tid; e < strip_elems; e += 256) {
        const int oyr = e / (OUT_W * CH);
        const int rem = e - oyr * (OUT_W * CH);             // ox*CH + c
        const int n = vn[oyr];
        const int l = vlo[oyr];
        float acc = 0.0f;
        #pragma unroll 6
        for (int t = 0; t < n; t++)
            acc = fmaf(vw[oyr][t], sm[SM_MID + (l + t) * (OUT_W * CH) + rem], acc);
        out[(((size_t)b * OUT_H + oy0 + oyr) * OUT_W * CH) + rem] = acc;
    }
}

extern "C" void kernel_launch(void* const* d_in, const int* in_sizes, int n_in,
                              void* d_out, int out_size) {
    const float* images = (const float*)d_in[0];   // (32, 512, 512, 3) f32
    const float* mats   = (const float*)d_in[1];   // (32, 2, 3) f32
    float* out          = (float*)d_out;           // (32, 224, 224, 3) f32

    static bool attr_set = false;
    if (!attr_set) {
        cudaFuncSetAttribute(fused_warp_resize_kernel,
                             cudaFuncAttributeMaxDynamicSharedMemorySize,
                             SM_FLOATS * (int)sizeof(float));
        attr_set = true;   // set once, outside graph capture (harness's first correctness call)
    }

    dim3 grid(NBLK, BATCH);
    fused_warp_resize_kernel<<<grid, 256, SM_FLOATS * sizeof(float)>>>(images, mats, out);
}

// round 15
// speedup vs baseline: 1.0951x; 1.0951x over previous
#include <cuda_runtime.h>
#include <cuda_bf16.h>

#define BATCH 32
#define IN_H  512
#define IN_W  512
#define CH    3
#define OUT_H 224
#define OUT_W 224

#define STRIP    8                      // output rows per CTA
#define MAXROWS  22                     // max mid rows per strip (span <= 20.6 -> 21 rows)
#define NBLK     (OUT_H / STRIP)        // 28
#define INVS     (16.0f / 7.0f)         // in/out scale (both dims) = antialias kernel radius

// jax.image.resize "bilinear", antialias=True, downscale by 16/7:
// sample = (o+0.5)*INVS - 0.5 ; triangle widened to radius INVS;
// weights over in-range taps, normalized to sum 1.
__device__ __forceinline__ int resize_weights(int o, int in_size, int& jlo, float w[6]) {
    const float sample = (o + 0.5f) * INVS - 0.5f;
    int lo = (int)ceilf(sample - INVS);
    int hi = (int)floorf(sample + INVS);
    if (lo < 0) lo = 0;
    if (hi > in_size - 1) hi = in_size - 1;
    const int n = hi - lo + 1;
    float sum = 0.0f;
    #pragma unroll 6
    for (int t = 0; t < n; t++) {
        float wt = 1.0f - fabsf(sample - (float)(lo + t)) * (7.0f / 16.0f);
        wt = fmaxf(wt, 0.0f);
        w[t] = wt;
        sum += wt;
    }
    const float inv = 1.0f / sum;
    #pragma unroll 6
    for (int t = 0; t < n; t++) w[t] *= inv;
    jlo = lo;
    return n;
}

__global__ __launch_bounds__(256, 4) void fused_warp_resize_kernel(
    const float* __restrict__ images,
    const float* __restrict__ mats,
    float* __restrict__ out)
{
    __shared__ float srow[2][CH][IN_W];          // warped-row ping-pong, 12.3 KB
    __shared__ float wtab[MAXROWS][STRIP];       // vertical weight: mid row r -> output oyr
    __shared__ float Ms[6];

    const int tid = threadIdx.x;
    const int b   = blockIdx.y;
    const int oy0 = blockIdx.x * STRIP;

    // ---- source-resolution row range needed by this strip of 8 output rows
    const float s_first = (oy0 + 0.5f) * INVS - 0.5f;
    const float s_last  = (oy0 + STRIP - 0.5f) * INVS - 0.5f;
    int jlo = (int)ceilf(s_first - INVS);  if (jlo < 0) jlo = 0;
    int jhi = (int)floorf(s_last + INVS);  if (jhi > IN_H - 1) jhi = IN_H - 1;
    const int nrows = jhi - jlo + 1;       // <= 21

    if (tid < 6) Ms[tid] = mats[b * 6 + tid];

    // vertical weight table: wtab[r][oyr] = weight of mid row (jlo+r) in output row (oy0+oyr)
    if (tid < MAXROWS * STRIP) {
        const int r   = tid / STRIP;
        const int oyr = tid - r * STRIP;
        int l; float w[6];
        const int n = resize_weights(oy0 + oyr, IN_H, l, w);
        const int t = (jlo + r) - l;
        wtab[r][oyr] = (r < nrows && t >= 0 && t < n) ? w[t] : 0.0f;
    }

    // horizontal weights: ox == tid is fixed across rows -> registers, once
    int   hlo = 0, hn = 0;
    float hw[6];
    if (tid < OUT_W) hn = resize_weights(tid, IN_W, hlo, hw);

    __syncthreads();
    const float M00 = Ms[0], M01 = Ms[1], M02 = Ms[2];
    const float M10 = Ms[3], M11 = Ms[4], M12 = Ms[5];
    const float* __restrict__ img = images + (size_t)b * IN_H * IN_W * CH;

    // per-thread vertical accumulators: output column ox=tid, 8 rows x 3 channels
    float acc[STRIP][CH];
    #pragma unroll
    for (int i = 0; i < STRIP; i++)
        #pragma unroll
        for (int c = 0; c < CH; c++) acc[i][c] = 0.0f;

    // ---- per mid row: warp 512 px (phase 1), h-resize + vertical FMA (phase 2).
    // One barrier per row: phase-1 of row r+1 writes the opposite srow buffer from
    // the one phase-2 stragglers of row r read; the WAR on buffer r&1 at row r+2
    // is ordered by the intervening barrier.
    for (int r = 0; r < nrows; r++) {
        float (* __restrict__ sr)[IN_W] = srow[r & 1];
        const float fj = (float)(jlo + r);
        const float by = fmaf(M00, fj, M02);
        const float bx = fmaf(M10, fj, M12);

        #pragma unroll
        for (int half = 0; half < 2; half++) {
            const int x = tid + half * 256;
            const float fx = (float)x;
            const float sy = fmaf(M01, fx, by);
            const float sx = fmaf(M11, fx, bx);
            const float y0f = floorf(sy);
            const float x0f = floorf(sx);
            float wy = sy - y0f;
            float wx = sx - x0f;
            const int y0 = (int)y0f;
            const int x0 = (int)x0f;

            // fold the zero-pad validity into the interpolation weights:
            //   row y0 invalid  -> its contribution weight (1-wy) := 0
            //   row y0+1 invalid-> wy := 0
            //   col x0 invalid  -> (1-wx) := 0 ; col x0+1 invalid -> wx := 0
            float owy = 1.0f - wy;
            float owx = 1.0f - wx;
            if (y0 < 0 || y0 >= IN_H)           owy = 0.0f;
            if (y0 + 1 < 0 || y0 + 1 >= IN_H)   wy  = 0.0f;
            if (x0 < 0 || x0 >= IN_W)           owx = 0.0f;
            if (x0 + 1 < 0 || x0 + 1 >= IN_W)   wx  = 0.0f;

            const int yc0 = min(max(y0, 0), IN_H - 1);
            const int yc1 = min(max(y0 + 1, 0), IN_H - 1);
            const int xc0 = min(max(x0, 0), IN_W - 1);
            const int xc1 = min(max(x0 + 1, 0), IN_W - 1);

            const float* __restrict__ r0 = img + ((size_t)yc0 * IN_W) * CH;
            const float* __restrict__ r1 = img + ((size_t)yc1 * IN_W) * CH;
            const int o00 = xc0 * CH, o01 = xc1 * CH;

            #pragma unroll
            for (int c = 0; c < CH; c++) {
                const float v00 = __ldg(r0 + o00 + c);
                const float v01 = __ldg(r0 + o01 + c);
                const float v10 = __ldg(r1 + o00 + c);
                const float v11 = __ldg(r1 + o01 + c);
                const float top = fmaf(v00, owx, v01 * wx);
                const float bot = fmaf(v10, owx, v11 * wx);
                sr[c][x] = fmaf(top, owy, bot * wy);
            }
        }
        __syncthreads();    // srow[r&1] ready for readers

        if (tid < OUT_W) {
            float a0 = 0.0f, a1 = 0.0f, a2 = 0.0f;
            #pragma unroll 6
            for (int t = 0; t < hn; t++) {
                const float wt = hw[t];
                const int j = hlo + t;
                a0 = fmaf(wt, sr[0][j], a0);
                a1 = fmaf(wt, sr[1][j], a1);
                a2 = fmaf(wt, sr[2][j], a2);
            }
            // vertical accumulation: unrolled over all 8 output rows (compile-time
            // acc indices; weights zero outside each row's <=3-row window)
            #pragma unroll
            for (int oyr = 0; oyr < STRIP; oyr++) {
                const float wv = wtab[r][oyr];
                acc[oyr][0] = fmaf(wv, a0, acc[oyr][0]);
                acc[oyr][1] = fmaf(wv, a1, acc[oyr][1]);
                acc[oyr][2] = fmaf(wv, a2, acc[oyr][2]);
            }
        }
        // no second barrier: next row writes the other srow buffer
    }

    // ---- write the 8 output rows for this column
    if (tid < OUT_W) {
        #pragma unroll
        for (int oyr = 0; oyr < STRIP; oyr++) {
            float* __restrict__ o =
                out + (((size_t)b * OUT_H + oy0 + oyr) * OUT_W + tid) * CH;
            o[0] = acc[oyr][0];
            o[1] = acc[oyr][1];
            o[2] = acc[oyr][2];
        }
    }
}

extern "C" void kernel_launch(void* const* d_in, const int* in_sizes, int n_in,
                              void* d_out, int out_size) {
    const float* images = (const float*)d_in[0];   // (32, 512, 512, 3) f32
    const float* mats   = (const float*)d_in[1];   // (32, 2, 3) f32
    float* out          = (float*)d_out;           // (32, 224, 224, 3) f32

    dim3 grid(NBLK, BATCH);
    fused_warp_resize_kernel<<<grid, 256>>>(images, mats, out);
}